// round 3
// baseline (speedup 1.0000x reference)
#include <cuda_runtime.h>
#include <cstdint>

// Sparsemax along last dim (d = 4096) via Michelot's finite-termination
// threshold algorithm (no sort):
//   tau_0 = (sum(x) - 1) / d
//   tau_{t+1} = (sum_{x_i > tau_t} x_i - 1) / |{x_i > tau_t}|
//   stop when active-set count is unchanged  ->  tau = tau*, out = max(x - tau, 0)
//
// One CTA per row. Row (4096 fp32 = 16 KB) lives in registers:
// 256 threads x 4 float4 = 16 floats/thread. Iterations touch only
// registers + shuffles, so the kernel stays HBM-bound (read + write once).

#define ROW_D     4096
#define THREADS   256
#define V4_PER_T  4    // 4 float4 = 16 floats per thread

__global__ __launch_bounds__(THREADS, 4)
void sparsemax_kernel(const float* __restrict__ x, float* __restrict__ out)
{
    const size_t row_base = (size_t)blockIdx.x * ROW_D;
    const float4* __restrict__ xr  = reinterpret_cast<const float4*>(x + row_base);
    float4*       __restrict__ orr = reinterpret_cast<float4*>(out + row_base);

    const int tid = threadIdx.x;

    // ---- load row into registers (coalesced float4, stride THREADS) ----
    float4 v4[V4_PER_T];
#pragma unroll
    for (int i = 0; i < V4_PER_T; ++i)
        v4[i] = xr[tid + i * THREADS];

    __shared__ float s_sum[THREADS / 32];
    __shared__ float s_cnt[THREADS / 32];
    __shared__ float s_tau;
    __shared__ int   s_count;

    const int wid = tid >> 5;
    const int lid = tid & 31;

    float tau    = -3.4e38f;  // first pass = full-set mean
    int   prev_c = -1;

    // Michelot iterations (finite termination; cap for safety)
    for (int iter = 0; iter < 64; ++iter) {
        float s = 0.0f, c = 0.0f;
#pragma unroll
        for (int i = 0; i < V4_PER_T; ++i) {
            const float4 q = v4[i];
            if (q.x > tau) { s += q.x; c += 1.0f; }
            if (q.y > tau) { s += q.y; c += 1.0f; }
            if (q.z > tau) { s += q.z; c += 1.0f; }
            if (q.w > tau) { s += q.w; c += 1.0f; }
        }
        // warp butterfly reduce
#pragma unroll
        for (int o = 16; o > 0; o >>= 1) {
            s += __shfl_xor_sync(0xFFFFFFFFu, s, o);
            c += __shfl_xor_sync(0xFFFFFFFFu, c, o);
        }
        if (lid == 0) { s_sum[wid] = s; s_cnt[wid] = c; }
        __syncthreads();
        if (tid == 0) {
            float S = 0.0f, C = 0.0f;
#pragma unroll
            for (int w = 0; w < THREADS / 32; ++w) { S += s_sum[w]; C += s_cnt[w]; }
            s_tau   = (S - 1.0f) / C;   // C >= 1 always (tau < tau* => support nonempty)
            s_count = (int)C;
        }
        __syncthreads();
        tau = s_tau;
        const int cnt = s_count;
        if (cnt == prev_c) break;       // uniform across CTA
        prev_c = cnt;
        __syncthreads();                // s_sum/s_cnt reuse vs. s_tau/s_count reads
    }

    // ---- epilogue: out = max(x - tau, 0), coalesced float4 stores ----
#pragma unroll
    for (int i = 0; i < V4_PER_T; ++i) {
        const float4 q = v4[i];
        float4 o;
        o.x = fmaxf(q.x - tau, 0.0f);
        o.y = fmaxf(q.y - tau, 0.0f);
        o.z = fmaxf(q.z - tau, 0.0f);
        o.w = fmaxf(q.w - tau, 0.0f);
        orr[tid + i * THREADS] = o;
    }
}

extern "C" void kernel_launch(void* const* d_in, const int* in_sizes, int n_in,
                              void* d_out, int out_size)
{
    const float* x   = (const float*)d_in[0];
    float*       out = (float*)d_out;
    const int n_rows = in_sizes[0] / ROW_D;   // 4 * 4096 = 16384
    sparsemax_kernel<<<n_rows, THREADS>>>(x, out);
}

// round 4
// speedup vs baseline: 1.6002x; 1.6002x over previous
#include <cuda_runtime.h>
#include <cstdint>
#include <cfloat>

// Sparsemax (d = 4096) via max-seeded shrinking-set Michelot:
//   M   = max(row);  thr_0 = M - 1          (provably <= tau*, support ⊆ A0)
//   tau = (sum_{x>thr} x - 1)/|{x>thr}| ;  thr = max(thr, tau)
//   stop when active count unchanged -> tau exact; out = max(x - tau, 0)
//
// One CTA per row; row resident in registers (256 thr x 4 float4).
// ~3-4 Michelot iterations for Gaussian rows (vs ~10 from mean seed).
// One __syncthreads per reduction via double-buffered smem + redundant
// all-thread final reduce.

#define ROW_D     4096
#define THREADS   256
#define NW        (THREADS / 32)
#define V4_PER_T  4

__global__ __launch_bounds__(THREADS, 5)
void sparsemax_kernel(const float* __restrict__ x, float* __restrict__ out)
{
    const size_t row_base = (size_t)blockIdx.x * ROW_D;
    const float4* __restrict__ xr  = reinterpret_cast<const float4*>(x + row_base);
    float4*       __restrict__ orr = reinterpret_cast<float4*>(out + row_base);

    const int tid = threadIdx.x;
    const int wid = tid >> 5;
    const int lid = tid & 31;

    // ---- load row into registers (coalesced float4) ----
    float4 v4[V4_PER_T];
#pragma unroll
    for (int i = 0; i < V4_PER_T; ++i)
        v4[i] = xr[tid + i * THREADS];

    __shared__ float  s_max[NW];
    __shared__ float2 s_red[2][NW];   // double-buffered (sum, count)

    // ---- pass 1: row max ----
    float m = -FLT_MAX;
#pragma unroll
    for (int i = 0; i < V4_PER_T; ++i) {
        const float4 q = v4[i];
        m = fmaxf(m, fmaxf(fmaxf(q.x, q.y), fmaxf(q.z, q.w)));
    }
#pragma unroll
    for (int o = 16; o > 0; o >>= 1)
        m = fmaxf(m, __shfl_xor_sync(0xFFFFFFFFu, m, o));
    if (lid == 0) s_max[wid] = m;
    __syncthreads();
    float M = s_max[0];
#pragma unroll
    for (int w = 1; w < NW; ++w) M = fmaxf(M, s_max[w]);

    // ---- seeded shrinking Michelot ----
    float thr    = M - 1.0f;   // tau* >= M - 1 always
    float tau    = thr;
    int   prev_c = -1;

    for (int iter = 0; iter < 32; ++iter) {
        float s = 0.0f, c = 0.0f;
#pragma unroll
        for (int i = 0; i < V4_PER_T; ++i) {
            const float4 q = v4[i];
            if (q.x > thr) { s += q.x; c += 1.0f; }
            if (q.y > thr) { s += q.y; c += 1.0f; }
            if (q.z > thr) { s += q.z; c += 1.0f; }
            if (q.w > thr) { s += q.w; c += 1.0f; }
        }
#pragma unroll
        for (int o = 16; o > 0; o >>= 1) {
            s += __shfl_xor_sync(0xFFFFFFFFu, s, o);
            c += __shfl_xor_sync(0xFFFFFFFFu, c, o);
        }
        const int buf = iter & 1;
        if (lid == 0) s_red[buf][wid] = make_float2(s, c);
        __syncthreads();

        // redundant all-thread final reduce (deterministic -> uniform branch)
        float S = 0.0f, C = 0.0f;
#pragma unroll
        for (int w = 0; w < NW; ++w) {
            const float2 r = s_red[buf][w];
            S += r.x;  C += r.y;
        }
        tau = (S - 1.0f) / C;          // C >= 1: max element always > thr
        const int cnt = (int)C;
        if (cnt == prev_c) break;      // set unchanged -> tau exact
        prev_c = cnt;
        thr = fmaxf(thr, tau);         // shrinking-set invariant
    }

    // ---- epilogue: out = max(x - tau, 0) ----
#pragma unroll
    for (int i = 0; i < V4_PER_T; ++i) {
        const float4 q = v4[i];
        float4 o;
        o.x = fmaxf(q.x - tau, 0.0f);
        o.y = fmaxf(q.y - tau, 0.0f);
        o.z = fmaxf(q.z - tau, 0.0f);
        o.w = fmaxf(q.w - tau, 0.0f);
        orr[tid + i * THREADS] = o;
    }
}

extern "C" void kernel_launch(void* const* d_in, const int* in_sizes, int n_in,
                              void* d_out, int out_size)
{
    const float* x   = (const float*)d_in[0];
    float*       out = (float*)d_out;
    const int n_rows = in_sizes[0] / ROW_D;   // 16384
    sparsemax_kernel<<<n_rows, THREADS>>>(x, out);
}

// round 5
// speedup vs baseline: 1.7793x; 1.1119x over previous
#include <cuda_runtime.h>
#include <cstdint>
#include <cfloat>

// Sparsemax (d = 4096), max-seeded Michelot with candidate compaction:
//   M = max(row); thr0 = M - 1  (tau* >= M-1, support subset of {x > thr0})
//   Pass 1 doubles as compaction (survivors -> smem) + Michelot iter 1.
//   Remaining iterations: warp 0 only, over the ~60-element compacted set.
//   out = max(x - tau, 0).
// Row resident in registers (256 thr x 4 float4); HBM touched once each way.

#define ROW_D     4096
#define THREADS   256
#define NW        (THREADS / 32)
#define V4_PER_T  4

__global__ __launch_bounds__(THREADS, 6)
void sparsemax_kernel(const float* __restrict__ x, float* __restrict__ out)
{
    __shared__ float  s_max[NW];
    __shared__ float2 s_sc[NW];
    __shared__ int    s_n;
    __shared__ float  s_tau;
    __shared__ float  s_buf[ROW_D];   // worst case: all elements survive

    const size_t row_base = (size_t)blockIdx.x * ROW_D;
    const float4* __restrict__ xr  = reinterpret_cast<const float4*>(x + row_base);
    float4*       __restrict__ orr = reinterpret_cast<float4*>(out + row_base);

    const int tid = threadIdx.x;
    const int wid = tid >> 5;
    const int lid = tid & 31;

    // ---- load row into registers ----
    float4 v4[V4_PER_T];
#pragma unroll
    for (int i = 0; i < V4_PER_T; ++i)
        v4[i] = xr[tid + i * THREADS];

    // ---- pass 1a: row max ----
    float m = -FLT_MAX;
#pragma unroll
    for (int i = 0; i < V4_PER_T; ++i) {
        const float4 q = v4[i];
        m = fmaxf(m, fmaxf(fmaxf(q.x, q.y), fmaxf(q.z, q.w)));
    }
#pragma unroll
    for (int o = 16; o > 0; o >>= 1)
        m = fmaxf(m, __shfl_xor_sync(0xFFFFFFFFu, m, o));
    if (lid == 0) s_max[wid] = m;
    if (tid == 0) s_n = 0;
    __syncthreads();

    float M = s_max[0];
#pragma unroll
    for (int w = 1; w < NW; ++w) M = fmaxf(M, s_max[w]);
    const float thr0 = M - 1.0f;

    // ---- pass 1b: compact survivors + accumulate (sum, count) ----
    float s = 0.0f, c = 0.0f;
    int   myc = 0;
#pragma unroll
    for (int i = 0; i < V4_PER_T; ++i) {
        const float4 q = v4[i];
        if (q.x > thr0) { s += q.x; c += 1.0f; ++myc; }
        if (q.y > thr0) { s += q.y; c += 1.0f; ++myc; }
        if (q.z > thr0) { s += q.z; c += 1.0f; ++myc; }
        if (q.w > thr0) { s += q.w; c += 1.0f; ++myc; }
    }
    if (myc > 0) {
        int pos = atomicAdd(&s_n, myc);
#pragma unroll
        for (int i = 0; i < V4_PER_T; ++i) {
            const float4 q = v4[i];
            if (q.x > thr0) s_buf[pos++] = q.x;
            if (q.y > thr0) s_buf[pos++] = q.y;
            if (q.z > thr0) s_buf[pos++] = q.z;
            if (q.w > thr0) s_buf[pos++] = q.w;
        }
    }
#pragma unroll
    for (int o = 16; o > 0; o >>= 1) {
        s += __shfl_xor_sync(0xFFFFFFFFu, s, o);
        c += __shfl_xor_sync(0xFFFFFFFFu, c, o);
    }
    if (lid == 0) s_sc[wid] = make_float2(s, c);
    __syncthreads();

    // ---- warp 0: Michelot iterations over the compacted set ----
    if (wid == 0) {
        float S = 0.0f, C = 0.0f;
#pragma unroll
        for (int w = 0; w < NW; ++w) { S += s_sc[w].x; C += s_sc[w].y; }
        const int n = s_n;

        float tau  = (S - 1.0f) / C;   // iteration 1 (set = all survivors)
        int   prev = (int)C;

        for (int iter = 0; iter < 32; ++iter) {
            float ls = 0.0f, lc = 0.0f;
            for (int j = lid; j < n; j += 32) {
                const float v = s_buf[j];
                if (v > tau) { ls += v; lc += 1.0f; }
            }
#pragma unroll
            for (int o = 16; o > 0; o >>= 1) {
                ls += __shfl_xor_sync(0xFFFFFFFFu, ls, o);
                lc += __shfl_xor_sync(0xFFFFFFFFu, lc, o);
            }
            const int cnt = (int)lc;        // >= 1: M always > tau (tau <= tau* < M)
            const float ntau = (ls - 1.0f) / lc;
            if (cnt == prev) { tau = ntau; break; }
            prev = cnt;
            tau  = ntau;                    // non-decreasing from M-1 seed
        }
        if (lid == 0) s_tau = tau;
    }
    __syncthreads();

    const float tau = s_tau;

    // ---- epilogue: out = max(x - tau, 0) ----
#pragma unroll
    for (int i = 0; i < V4_PER_T; ++i) {
        const float4 q = v4[i];
        float4 o;
        o.x = fmaxf(q.x - tau, 0.0f);
        o.y = fmaxf(q.y - tau, 0.0f);
        o.z = fmaxf(q.z - tau, 0.0f);
        o.w = fmaxf(q.w - tau, 0.0f);
        orr[tid + i * THREADS] = o;
    }
}

extern "C" void kernel_launch(void* const* d_in, const int* in_sizes, int n_in,
                              void* d_out, int out_size)
{
    const float* x   = (const float*)d_in[0];
    float*       out = (float*)d_out;
    const int n_rows = in_sizes[0] / ROW_D;   // 16384
    sparsemax_kernel<<<n_rows, THREADS>>>(x, out);
}